// round 12
// baseline (speedup 1.0000x reference)
#include <cuda_runtime.h>
#include <cuda_fp16.h>
#include <cstdint>
#include <string.h>

typedef unsigned long long ull;
typedef unsigned int uint;

#define L    64
#define NGR  8192
#define HD   128
#define MM   64             // graphs per CTA
#define NTH  512            // 16 warps

// ---- smem byte offsets ----
#define S_A    0            // A: 64 rows x 256 k fp16, SW128 blocked (32KB)
#define S_W0   32768        // resident W image 0 (64KB)
#define S_WB0  98304        // W stream buf 0 (64KB)
#define S_WB1  163840       // W stream buf 1 (64KB)
#define S_TOT  229376       // 224KB

// W images: 4 jobs (k64 slices of K=256). Each: [512 n][64 k] fp16, SW128. 64KB.
__device__ __align__(128) unsigned char wblob[4 * 65536];
__device__ float hs_buf[(size_t)NGR * L * HD];   // 256MB hidden states

// ---- PTX helpers (base PTX; no tcgen05 on this toolchain) ----
__device__ __forceinline__ uint smem_u32(const void* p) {
    uint a; asm("{ .reg .u64 t; cvta.to.shared.u64 t, %1; cvt.u32.u64 %0, t; }"
                : "=r"(a) : "l"(p));
    return a;
}
#define CP_ASYNC16(dst, src) \
    asm volatile("cp.async.cg.shared.global [%0], [%1], 16;" :: "r"(dst), "l"(src))
#define CP_COMMIT() asm volatile("cp.async.commit_group;" ::: "memory")
#define CP_WAIT(n)  asm volatile("cp.async.wait_group %0;" :: "n"(n) : "memory")

__device__ __forceinline__ void ldmx4(uint* r, uint addr) {
    asm volatile("ldmatrix.sync.aligned.m8n8.x4.shared.b16 {%0,%1,%2,%3}, [%4];"
        : "=r"(r[0]), "=r"(r[1]), "=r"(r[2]), "=r"(r[3]) : "r"(addr));
}
__device__ __forceinline__ void mma16816(float* d, const uint* a, const uint* b) {
    asm volatile(
        "mma.sync.aligned.m16n8k16.row.col.f32.f16.f16.f32 "
        "{%0,%1,%2,%3}, {%4,%5,%6,%7}, {%8,%9}, {%0,%1,%2,%3};"
        : "+f"(d[0]), "+f"(d[1]), "+f"(d[2]), "+f"(d[3])
        : "r"(a[0]), "r"(a[1]), "r"(a[2]), "r"(a[3]), "r"(b[0]), "r"(b[1]));
}
// ---- MUFU activations ----
__device__ __forceinline__ float ex2a(float x) { float y; asm("ex2.approx.f32 %0, %1;" : "=f"(y) : "f"(x)); return y; }
__device__ __forceinline__ float rcpa(float x) { float y; asm("rcp.approx.f32 %0, %1;" : "=f"(y) : "f"(x)); return y; }
__device__ __forceinline__ float sigf(float x)  { return rcpa(1.0f + ex2a(-1.4426950408889634f * x)); }
__device__ __forceinline__ float tanhf_(float x){ return fmaf(2.0f, rcpa(1.0f + ex2a(-2.8853900817779268f * x)), -1.0f); }

__device__ __forceinline__ uint pk2h(float a, float b) {
    __half2 p = __floats2half2_rn(a, b);
    uint u; memcpy(&u, &p, 4); return u;
}
// A tile: 64 rows x 256 k fp16; atoms 8r x 64k; SW128 (32KB)
__device__ __forceinline__ uint a_off(int r, int k) {
    uint b = (uint)((((r >> 3) + (k >> 6) * 8) << 10) + ((r & 7) << 7) + ((k & 63) << 1));
    return b ^ ((b >> 3) & 0x70);
}
// W image: 512 n x 64 k fp16; atoms 8n x 64k (64KB)
__device__ __forceinline__ uint w_off(int n, int k) {
    uint b = (uint)(((n >> 3) << 10) + ((n & 7) << 7) + (k << 1));
    return b ^ ((b >> 3) & 0x70);
}

// ============ W prep: fp16 round, swizzle into 4 k64 images ============
extern "C" __global__ void prep_kernel(const float* __restrict__ W_ih,
                                       const float* __restrict__ W_hh)
{
    int i = blockIdx.x * blockDim.x + threadIdx.x;   // 512*256
    if (i >= 512 * 256) return;
    int n = i >> 8, gk = i & 255;                    // gk: x 0..127, h 128..255
    float w = (gk < 128) ? W_ih[n * 128 + gk] : W_hh[n * 128 + (gk - 128)];
    int job = gk >> 6, kk = gk & 63;
    *(__half*)(wblob + (size_t)job * 65536 + w_off(n, kk)) = __float2half_rn(w);
}

// ============ fused LSTM recurrence (mma.sync fp16) ============
extern "C" __global__ void __launch_bounds__(NTH, 1)
lstm_mma_kernel(const float* __restrict__ x,
                const float* __restrict__ b_ih,
                const float* __restrict__ b_hh)
{
    extern __shared__ __align__(1024) char sm[];
    const uint smb  = smem_u32(sm);
    const int tid   = threadIdx.x;
    const int lane  = tid & 31;
    const int warp  = tid >> 5;       // n-slice: 8 cols per gate
    const int graph0 = blockIdx.x * MM;

    // ldmatrix lane address components
    const int rA    = (lane & 7);
    const int mHalf = (lane >> 3) & 1;
    const int aKsel = (lane >> 4) << 4;
    const uint aPre = (uint)(rA << 7);
    const uint swA  = (uint)(rA << 4);
    // B x4: lane group (lane>>3) = tile 0..3 covering k bytes 0,16,32,48
    const uint bPre = (uint)((lane & 7) << 7) + ((uint)warp << 10);
    const uint swB  = (uint)((lane & 7) << 4);
    const uint bTile = (uint)((lane >> 3) << 4);
    const int jj   = (lane & 3) << 1;
    const int j0   = (warp << 3) + jj;
    const int rowq = lane >> 2;

    // bias seeds
    float bseed[4][2];
    #pragma unroll
    for (int gt = 0; gt < 4; gt++) {
        bseed[gt][0] = b_ih[gt * 128 + j0]     + b_hh[gt * 128 + j0];
        bseed[gt][1] = b_ih[gt * 128 + j0 + 1] + b_hh[gt * 128 + j0 + 1];
    }

    // load resident W image 0
    {
        const char* src = (const char*)wblob + tid * 16;
        uint dst = smb + S_W0 + tid * 16;
        #pragma unroll
        for (int it = 0; it < 8; it++)
            CP_ASYNC16(dst + it * 8192, src + it * 8192);
        CP_COMMIT();
    }
    // zero h-region of A (k 128..255 = bytes [16384,32768))
    #pragma unroll
    for (int it = 0; it < 4; it++)
        ((ull*)(sm + S_A + 16384))[tid + it * NTH] = 0ull;

    float creg[4][4];
    #pragma unroll
    for (int a = 0; a < 4; a++)
        #pragma unroll
        for (int b = 0; b < 4; b++) creg[a][b] = 0.0f;

    CP_WAIT(0);
    __syncthreads();   // resident W + h-zero visible

    for (int t = 0; t < L; t++) {
        // ---- stage x_t: 64 graphs x 128 fp32 -> A k[0..127] fp16 ----
        // (safe: prior step's MMAs all done at S4; x/h regions disjoint)
        #pragma unroll
        for (int it = 0; it < 4; it++) {
            int idx = tid + it * NTH;
            int g = idx >> 5, v = idx & 31;
            float4 xv = *(const float4*)(x + ((size_t)(graph0 + g) * L + t) * HD + v * 4);
            *(ull*)(sm + S_A + a_off(g, v * 4)) =
                (ull)pk2h(xv.x, xv.y) | ((ull)pk2h(xv.z, xv.w) << 32);
        }
        // accumulators seeded with bias
        float acc[4][4][4];
        #pragma unroll
        for (int mt = 0; mt < 4; mt++)
            #pragma unroll
            for (int gt = 0; gt < 4; gt++) {
                acc[mt][gt][0] = bseed[gt][0]; acc[mt][gt][1] = bseed[gt][1];
                acc[mt][gt][2] = bseed[gt][0]; acc[mt][gt][3] = bseed[gt][1];
            }
        __syncthreads();   // S0: x + h writes visible; WB0/WB1 free

        // issue img1 -> WB0, img2 -> WB1 (overlap with job0)
        {
            const char* s1 = (const char*)wblob + 65536 + tid * 16;
            const char* s2 = (const char*)wblob + 131072 + tid * 16;
            uint d1 = smb + S_WB0 + tid * 16;
            uint d2 = smb + S_WB1 + tid * 16;
            #pragma unroll
            for (int it = 0; it < 8; it++)
                CP_ASYNC16(d1 + it * 8192, s1 + it * 8192);
            CP_COMMIT();
            #pragma unroll
            for (int it = 0; it < 8; it++)
                CP_ASYNC16(d2 + it * 8192, s2 + it * 8192);
            CP_COMMIT();
        }

        // ---- 4 jobs; job j reads A atom-col j and W image j ----
        #pragma unroll
        for (int j = 0; j < 4; j++) {
            uint wb;
            if (j == 0) {
                wb = smb + S_W0;                     // resident, no wait
            } else if (j == 1) {
                CP_WAIT(1); __syncthreads();         // S1: img1 visible
                wb = smb + S_WB0;
            } else if (j == 2) {
                CP_WAIT(0); __syncthreads();         // S2: img2 visible; job1 done
                // issue img3 -> WB0 (freed by job1)
                const char* s3 = (const char*)wblob + 196608 + tid * 16;
                uint d3 = smb + S_WB0 + tid * 16;
                #pragma unroll
                for (int it = 0; it < 8; it++)
                    CP_ASYNC16(d3 + it * 8192, s3 + it * 8192);
                CP_COMMIT();
                wb = smb + S_WB1;
            } else {
                CP_WAIT(0); __syncthreads();         // S3: img3 visible
                wb = smb + S_WB0;
            }
            const uint aAtomBase = (uint)((mHalf + j * 8) << 10);

            #pragma unroll
            for (int k32 = 0; k32 < 2; k32++) {
                // B frags: ldmx4 per gate = k32 worth (2 k16 slices)
                uint bfr[4][4];
                const uint bLow = (uint)((k32 << 6) + bTile) ^ swB;
                #pragma unroll
                for (int gt = 0; gt < 4; gt++)
                    ldmx4(bfr[gt], wb + (uint)(gt << 14) + bPre + bLow);
                #pragma unroll
                for (int k16 = 0; k16 < 2; k16++) {
                    const uint aLow =
                        (uint)((((k32 << 1) + k16) << 5) + aKsel) ^ swA;
                    #pragma unroll
                    for (int mt = 0; mt < 4; mt++) {
                        uint ah[4];
                        ldmx4(ah, smb + S_A + aAtomBase + (uint)(mt << 11) + aPre + aLow);
                        #pragma unroll
                        for (int gt = 0; gt < 4; gt++)
                            mma16816(acc[mt][gt], ah, &bfr[gt][k16 * 2]);
                    }
                }
            }
        }
        __syncthreads();   // S4: all MMAs done -> h/x regions writable

        // ---- epilogue: lane-local LSTM update; h -> A fp16 + hs_buf fp32 ----
        #pragma unroll
        for (int mt = 0; mt < 4; mt++) {
            #pragma unroll
            for (int rg = 0; rg < 2; rg++) {
                float h2[2];
                #pragma unroll
                for (int cp = 0; cp < 2; cp++) {
                    const int fr = rg * 2 + cp;
                    float iv = sigf (acc[mt][0][fr]);
                    float fv = sigf (acc[mt][1][fr]);
                    float gv = tanhf_(acc[mt][2][fr]);
                    float ov = sigf (acc[mt][3][fr]);
                    float c  = fv * creg[mt][fr] + iv * gv;
                    creg[mt][fr] = c;
                    h2[cp] = ov * tanhf_(c);
                }
                const int g = mt * 16 + rg * 8 + rowq;
                *(uint*)(sm + S_A + a_off(g, 128 + j0)) = pk2h(h2[0], h2[1]);
                __stcs((float2*)(hs_buf + ((size_t)(graph0 + g) * L + t) * HD + j0),
                       make_float2(h2[0], h2[1]));
            }
        }
        // next iteration's S0 orders epilogue/x writes vs MMAs
    }
}

// ============ attention pooling: single pass over hs_buf ============
#define AG 4   // graphs per CTA
extern "C" __global__ void __launch_bounds__(256)
att_kernel(const float* __restrict__ W_att, const float* __restrict__ b_att,
           float* __restrict__ out)
{
    extern __shared__ float s[];
    float* Hs = s;                 // [4][64][128] = 32768 floats
    float* Sc = s + 32768;         // [4][64]
    float* Pp = s + 33024;         // [8][128]
    const int tid = threadIdx.x, lane = tid & 31, warp = tid >> 5;
    const int graph0 = blockIdx.x * AG;
    const float batt = b_att[0];
    const float4 wa4 = *(const float4*)(W_att + lane * 4);

    // stage h + compute scores in one pass
    #pragma unroll 4
    for (int it = 0; it < 32; it++) {
        const int g = it >> 3;
        const int t = (it & 7) * 8 + warp;
        float4 hv = __ldcs((const float4*)(hs_buf +
                        ((size_t)(graph0 + g) * L + t) * HD + lane * 4));
        *(float4*)(Hs + g * 8192 + t * 128 + lane * 4) = hv;
        float d = hv.x * wa4.x + hv.y * wa4.y + hv.z * wa4.z + hv.w * wa4.w;
        #pragma unroll
        for (int o = 16; o; o >>= 1)
            d += __shfl_xor_sync(0xffffffffu, d, o);
        if (lane == 0) Sc[g * 64 + t] = d + batt;
    }
    __syncthreads();

    if (warp < 4) {   // softmax per graph
        const int g = warp;
        float s1 = Sc[g * 64 + lane], s2 = Sc[g * 64 + 32 + lane];
        float m = fmaxf(s1, s2);
        #pragma unroll
        for (int o = 16; o; o >>= 1)
            m = fmaxf(m, __shfl_xor_sync(0xffffffffu, m, o));
        float e1 = ex2a(1.4426950408889634f * (s1 - m));
        float e2 = ex2a(1.4426950408889634f * (s2 - m));
        float z = e1 + e2;
        #pragma unroll
        for (int o = 16; o; o >>= 1)
            z += __shfl_xor_sync(0xffffffffu, z, o);
        float inv = rcpa(z);
        Sc[g * 64 + lane] = e1 * inv;
        Sc[g * 64 + 32 + lane] = e2 * inv;
    }
    __syncthreads();

    {   // weighted sum: warp w -> graph w>>1, t-half w&1
        const int g = warp >> 1;
        float4 a4 = make_float4(0.f, 0.f, 0.f, 0.f);
        #pragma unroll 4
        for (int tt = 0; tt < 32; tt++) {
            const int t = (warp & 1) * 32 + tt;
            float wt = Sc[g * 64 + t];
            float4 hv = *(const float4*)(Hs + g * 8192 + t * 128 + lane * 4);
            a4.x = fmaf(wt, hv.x, a4.x);
            a4.y = fmaf(wt, hv.y, a4.y);
            a4.z = fmaf(wt, hv.z, a4.z);
            a4.w = fmaf(wt, hv.w, a4.w);
        }
        *(float4*)(Pp + warp * 128 + lane * 4) = a4;
    }
    __syncthreads();

    {   // combine halves and write out
        const int g = tid >> 6, q = tid & 63;
        float v0 = Pp[(2 * g) * 128 + 2 * q]     + Pp[(2 * g + 1) * 128 + 2 * q];
        float v1 = Pp[(2 * g) * 128 + 2 * q + 1] + Pp[(2 * g + 1) * 128 + 2 * q + 1];
        *(float2*)(out + (size_t)(graph0 + g) * HD + 2 * q) = make_float2(v0, v1);
    }
}

extern "C" void kernel_launch(void* const* d_in, const int* in_sizes, int n_in,
                              void* d_out, int out_size)
{
    const float* x     = (const float*)d_in[0];
    // d_in[1] = batch (arange(N)//L), unused
    const float* W_ih  = (const float*)d_in[2];
    const float* W_hh  = (const float*)d_in[3];
    const float* b_ih  = (const float*)d_in[4];
    const float* b_hh  = (const float*)d_in[5];
    const float* W_att = (const float*)d_in[6];
    const float* b_att = (const float*)d_in[7];
    float* out = (float*)d_out;

    prep_kernel<<<512, 256>>>(W_ih, W_hh);
    cudaFuncSetAttribute(lstm_mma_kernel,
                         cudaFuncAttributeMaxDynamicSharedMemorySize, S_TOT);
    lstm_mma_kernel<<<NGR / MM, NTH, S_TOT>>>(x, b_ih, b_hh);
    const int att_smem = (32768 + 256 + 1024) * 4;   // Hs + Sc + Pp
    cudaFuncSetAttribute(att_kernel,
                         cudaFuncAttributeMaxDynamicSharedMemorySize, att_smem);
    att_kernel<<<NGR / AG, 256, att_smem>>>(W_att, b_att, out);
}

// round 13
// speedup vs baseline: 1.0992x; 1.0992x over previous
#include <cuda_runtime.h>
#include <cuda_fp16.h>
#include <cstdint>
#include <string.h>

typedef unsigned long long ull;
typedef unsigned int uint;

#define L    64
#define NGR  8192
#define HD   128
#define MM   32             // graphs per CTA
#define NTH  256            // 8 warps
#define AG   4

// ---- smem byte offsets ----
#define S_A    0            // A: 32 rows x 256 k fp16, SW128 blocked (16KB)
#define S_WB   16384        // 3-deep W image ring, 3 x 32KB
#define S_TOT  114688       // 112KB -> 2 CTAs/SM

// W images: 8 = kc(4) x nh(2). Image = [256 n'][64 k'] fp16 SW128, 32KB.
// n' = n - 256*nh (gates 2nh, 2nh+1), k' = k - 64*kc.
__device__ __align__(128) unsigned char wblob[8 * 32768];
__device__ float bsum[512];                      // b_ih + b_hh
__device__ float hs_buf[(size_t)NGR * L * HD];   // 256MB hidden states

// ---- PTX helpers (base PTX; no tcgen05 on this toolchain) ----
__device__ __forceinline__ uint smem_u32(const void* p) {
    uint a; asm("{ .reg .u64 t; cvta.to.shared.u64 t, %1; cvt.u32.u64 %0, t; }"
                : "=r"(a) : "l"(p));
    return a;
}
#define CP_ASYNC16(dst, src) \
    asm volatile("cp.async.cg.shared.global [%0], [%1], 16;" :: "r"(dst), "l"(src))
#define CP_COMMIT() asm volatile("cp.async.commit_group;" ::: "memory")
#define CP_WAIT(n)  asm volatile("cp.async.wait_group %0;" :: "n"(n) : "memory")

__device__ __forceinline__ void ldmx4(uint* r, uint addr) {
    asm volatile("ldmatrix.sync.aligned.m8n8.x4.shared.b16 {%0,%1,%2,%3}, [%4];"
        : "=r"(r[0]), "=r"(r[1]), "=r"(r[2]), "=r"(r[3]) : "r"(addr));
}
__device__ __forceinline__ void mma16816(float* d, const uint* a, const uint* b) {
    asm volatile(
        "mma.sync.aligned.m16n8k16.row.col.f32.f16.f16.f32 "
        "{%0,%1,%2,%3}, {%4,%5,%6,%7}, {%8,%9}, {%0,%1,%2,%3};"
        : "+f"(d[0]), "+f"(d[1]), "+f"(d[2]), "+f"(d[3])
        : "r"(a[0]), "r"(a[1]), "r"(a[2]), "r"(a[3]), "r"(b[0]), "r"(b[1]));
}
// ---- MUFU activations ----
__device__ __forceinline__ float ex2a(float x) { float y; asm("ex2.approx.f32 %0, %1;" : "=f"(y) : "f"(x)); return y; }
__device__ __forceinline__ float rcpa(float x) { float y; asm("rcp.approx.f32 %0, %1;" : "=f"(y) : "f"(x)); return y; }
__device__ __forceinline__ float sigf(float x)  { return rcpa(1.0f + ex2a(-1.4426950408889634f * x)); }
__device__ __forceinline__ float tanhf_(float x){ return fmaf(2.0f, rcpa(1.0f + ex2a(-2.8853900817779268f * x)), -1.0f); }

__device__ __forceinline__ uint pk2h(float a, float b) {
    __half2 p = __floats2half2_rn(a, b);
    uint u; memcpy(&u, &p, 4); return u;
}
// A tile: 32 r x 256 k fp16; atoms 8r x 64k; atom = (r>>3) + (k>>6)*4 (16KB)
__device__ __forceinline__ uint a_off(int r, int k) {
    uint b = (uint)((((r >> 3) + (k >> 6) * 4) << 10) + ((r & 7) << 7) + ((k & 63) << 1));
    return b ^ ((b >> 3) & 0x70);
}
// W image: 256 n' x 64 k' fp16; atoms 8n x 64k (32KB)
__device__ __forceinline__ uint w_off(int n, int k) {
    uint b = (uint)(((n >> 3) << 10) + ((n & 7) << 7) + (k << 1));
    return b ^ ((b >> 3) & 0x70);
}

// ============ W prep: fp16 round into 8 [256n][64k] images + bsum ============
extern "C" __global__ void prep_kernel(const float* __restrict__ W_ih,
                                       const float* __restrict__ W_hh,
                                       const float* __restrict__ b_ih,
                                       const float* __restrict__ b_hh)
{
    int i = blockIdx.x * blockDim.x + threadIdx.x;   // 512*256
    if (i >= 512 * 256) return;
    int n = i >> 8, gk = i & 255;                    // gk: x 0..127, h 128..255
    float w = (gk < 128) ? W_ih[n * 128 + gk] : W_hh[n * 128 + (gk - 128)];
    int img = ((gk >> 6) << 1) + (n >> 8);           // kc*2 + nh
    *(__half*)(wblob + (size_t)img * 32768 + w_off(n & 255, gk & 63)) =
        __float2half_rn(w);
    if (i < 512) bsum[i] = b_ih[i] + b_hh[i];
}

// ============ fused LSTM recurrence: 2 CTAs/SM ============
extern "C" __global__ void __launch_bounds__(NTH, 2)
lstm_mma_kernel(const float* __restrict__ x)
{
    extern __shared__ __align__(1024) char sm[];
    const uint smb  = smem_u32(sm);
    const int tid   = threadIdx.x;
    const int lane  = tid & 31;
    const int warp  = tid >> 5;       // 0..7: 16 n-cols per gate
    const int graph0 = blockIdx.x * MM;

    // ldmatrix lane address components
    const int rA    = (lane & 7);
    const int mHalf = (lane >> 3) & 1;
    const uint aKsel = (uint)((lane >> 4) << 4);
    const uint aPre = (uint)(rA << 7);
    const uint swA  = (uint)(rA << 4);
    const uint bPre = (uint)((lane & 7) << 7);
    const uint swB  = (uint)((lane & 7) << 4);
    const uint bTile = (uint)((lane >> 3) << 4);
    const int jj   = (lane & 3) << 1;
    const int rowq = lane >> 2;

    // zero h-region of A (k 128..255 = bytes [8192,16384))
    #pragma unroll
    for (int it = 0; it < 4; it++)
        ((ull*)(sm + S_A + 8192))[tid + it * NTH] = 0ull;

    float creg[2][2][4];               // [mt][nt][rg*2+cp]
    #pragma unroll
    for (int a = 0; a < 2; a++)
        #pragma unroll
        for (int b = 0; b < 2; b++)
            #pragma unroll
            for (int c = 0; c < 4; c++) creg[a][b][c] = 0.0f;

    for (int t = 0; t < L; t++) {
        // issue img0 -> ring0, img1 -> ring1 (prev step's MMAs all done)
        #pragma unroll
        for (int im = 0; im < 2; im++) {
            const char* src = (const char*)wblob + (size_t)im * 32768 + tid * 16;
            uint dst = smb + S_WB + im * 32768 + tid * 16;
            #pragma unroll
            for (int it = 0; it < 8; it++)
                CP_ASYNC16(dst + it * 4096, src + it * 4096);
            CP_COMMIT();
        }
        // stage x_t: 32 graphs x 128 fp32 -> A k[0..127] fp16
        #pragma unroll
        for (int it = 0; it < 4; it++) {
            int idx = tid + it * NTH;
            int g = idx >> 5, v = idx & 31;
            float4 xv = *(const float4*)(x + ((size_t)(graph0 + g) * L + t) * HD + v * 4);
            *(ull*)(sm + S_A + a_off(g, v * 4)) =
                (ull)pk2h(xv.x, xv.y) | ((ull)pk2h(xv.z, xv.w) << 32);
        }
        // acc seeded with bias (bsum is L1/L2-hot)
        float acc[2][4][2][4];         // [mt][gate][nt][frag]
        #pragma unroll
        for (int gt = 0; gt < 4; gt++)
            #pragma unroll
            for (int nt = 0; nt < 2; nt++) {
                float2 b = __ldg((const float2*)(bsum + gt * 128 + warp * 16 + nt * 8 + jj));
                #pragma unroll
                for (int mt = 0; mt < 2; mt++) {
                    acc[mt][gt][nt][0] = b.x; acc[mt][gt][nt][1] = b.y;
                    acc[mt][gt][nt][2] = b.x; acc[mt][gt][nt][3] = b.y;
                }
            }

        // ---- 8 jobs: j -> (kc = j>>1, nh = j&1), image ring j%3 ----
        #pragma unroll
        for (int j = 0; j < 8; j++) {
            if (j < 7) { CP_WAIT(1); } else { CP_WAIT(0); }
            __syncthreads();           // img j complete + visible; job j-1 done
            if (j <= 5) {              // issue img j+2 into ring (j+2)%3
                const char* src = (const char*)wblob + (size_t)(j + 2) * 32768 + tid * 16;
                uint dst = smb + S_WB + ((j + 2) % 3) * 32768 + tid * 16;
                #pragma unroll
                for (int it = 0; it < 8; it++)
                    CP_ASYNC16(dst + it * 4096, src + it * 4096);
                CP_COMMIT();
            }
            const int nh = j & 1, kc = j >> 1;
            const uint wb = smb + S_WB + (j % 3) * 32768;

            #pragma unroll
            for (int k32 = 0; k32 < 2; k32++) {
                uint bfr[2][2][4];     // [g01][nt]
                const uint bLow = (uint)((k32 << 6) + bTile) ^ swB;
                #pragma unroll
                for (int g01 = 0; g01 < 2; g01++)
                    #pragma unroll
                    for (int nt = 0; nt < 2; nt++)
                        ldmx4(bfr[g01][nt],
                              wb + (uint)((g01 * 16 + warp * 2 + nt) << 10) + bPre + bLow);
                #pragma unroll
                for (int k16 = 0; k16 < 2; k16++) {
                    const uint aLow = (uint)(((k32 * 2 + k16) << 5) + aKsel) ^ swA;
                    #pragma unroll
                    for (int mt = 0; mt < 2; mt++) {
                        uint ah[4];
                        ldmx4(ah, smb + S_A +
                              (uint)((2 * mt + mHalf + kc * 4) << 10) + aPre + aLow);
                        #pragma unroll
                        for (int g01 = 0; g01 < 2; g01++)
                            #pragma unroll
                            for (int nt = 0; nt < 2; nt++)
                                mma16816(acc[mt][2 * nh + g01][nt], ah,
                                         &bfr[g01][nt][k16 * 2]);
                    }
                }
            }
        }
        __syncthreads();               // all MMAs done -> A writable

        // ---- epilogue: lane-local LSTM update; h -> A fp16 + hs_buf fp32 ----
        #pragma unroll
        for (int mt = 0; mt < 2; mt++)
            #pragma unroll
            for (int rg = 0; rg < 2; rg++)
                #pragma unroll
                for (int nt = 0; nt < 2; nt++) {
                    float h2[2];
                    #pragma unroll
                    for (int cp = 0; cp < 2; cp++) {
                        const int fr = rg * 2 + cp;
                        float iv = sigf (acc[mt][0][nt][fr]);
                        float fv = sigf (acc[mt][1][nt][fr]);
                        float gv = tanhf_(acc[mt][2][nt][fr]);
                        float ov = sigf (acc[mt][3][nt][fr]);
                        float c  = fv * creg[mt][nt][fr] + iv * gv;
                        creg[mt][nt][fr] = c;
                        h2[cp] = ov * tanhf_(c);
                    }
                    const int g = mt * 16 + rg * 8 + rowq;
                    const int col0 = warp * 16 + nt * 8 + jj;
                    *(uint*)(sm + S_A + a_off(g, 128 + col0)) = pk2h(h2[0], h2[1]);
                    __stcs((float2*)(hs_buf + ((size_t)(graph0 + g) * L + t) * HD + col0),
                           make_float2(h2[0], h2[1]));
                }
        // next iteration's job-0 sync orders epilogue/x writes vs MMAs
    }
}

// ============ attention pooling: single pass over hs_buf ============
extern "C" __global__ void __launch_bounds__(256)
att_kernel(const float* __restrict__ W_att, const float* __restrict__ b_att,
           float* __restrict__ out)
{
    extern __shared__ float s[];
    float* Hs = s;                 // [4][64][128]
    float* Sc = s + 32768;         // [4][64]
    float* Pp = s + 33024;         // [8][128]
    const int tid = threadIdx.x, lane = tid & 31, warp = tid >> 5;
    const int graph0 = blockIdx.x * AG;
    const float batt = b_att[0];
    const float4 wa4 = *(const float4*)(W_att + lane * 4);

    #pragma unroll 4
    for (int it = 0; it < 32; it++) {
        const int g = it >> 3;
        const int t = (it & 7) * 8 + warp;
        float4 hv = __ldcs((const float4*)(hs_buf +
                        ((size_t)(graph0 + g) * L + t) * HD + lane * 4));
        *(float4*)(Hs + g * 8192 + t * 128 + lane * 4) = hv;
        float d = hv.x * wa4.x + hv.y * wa4.y + hv.z * wa4.z + hv.w * wa4.w;
        #pragma unroll
        for (int o = 16; o; o >>= 1)
            d += __shfl_xor_sync(0xffffffffu, d, o);
        if (lane == 0) Sc[g * 64 + t] = d + batt;
    }
    __syncthreads();

    if (warp < 4) {
        const int g = warp;
        float s1 = Sc[g * 64 + lane], s2 = Sc[g * 64 + 32 + lane];
        float m = fmaxf(s1, s2);
        #pragma unroll
        for (int o = 16; o; o >>= 1)
            m = fmaxf(m, __shfl_xor_sync(0xffffffffu, m, o));
        float e1 = ex2a(1.4426950408889634f * (s1 - m));
        float e2 = ex2a(1.4426950408889634f * (s2 - m));
        float z = e1 + e2;
        #pragma unroll
        for (int o = 16; o; o >>= 1)
            z += __shfl_xor_sync(0xffffffffu, z, o);
        float inv = rcpa(z);
        Sc[g * 64 + lane] = e1 * inv;
        Sc[g * 64 + 32 + lane] = e2 * inv;
    }
    __syncthreads();

    {
        const int g = warp >> 1;
        float4 a4 = make_float4(0.f, 0.f, 0.f, 0.f);
        #pragma unroll 4
        for (int tt = 0; tt < 32; tt++) {
            const int t = (warp & 1) * 32 + tt;
            float wt = Sc[g * 64 + t];
            float4 hv = *(const float4*)(Hs + g * 8192 + t * 128 + lane * 4);
            a4.x = fmaf(wt, hv.x, a4.x);
            a4.y = fmaf(wt, hv.y, a4.y);
            a4.z = fmaf(wt, hv.z, a4.z);
            a4.w = fmaf(wt, hv.w, a4.w);
        }
        *(float4*)(Pp + warp * 128 + lane * 4) = a4;
    }
    __syncthreads();

    {
        const int g = tid >> 6, q = tid & 63;
        float v0 = Pp[(2 * g) * 128 + 2 * q]     + Pp[(2 * g + 1) * 128 + 2 * q];
        float v1 = Pp[(2 * g) * 128 + 2 * q + 1] + Pp[(2 * g + 1) * 128 + 2 * q + 1];
        *(float2*)(out + (size_t)(graph0 + g) * HD + 2 * q) = make_float2(v0, v1);
    }
}

extern "C" void kernel_launch(void* const* d_in, const int* in_sizes, int n_in,
                              void* d_out, int out_size)
{
    const float* x     = (const float*)d_in[0];
    // d_in[1] = batch (arange(N)//L), unused
    const float* W_ih  = (const float*)d_in[2];
    const float* W_hh  = (const float*)d_in[3];
    const float* b_ih  = (const float*)d_in[4];
    const float* b_hh  = (const float*)d_in[5];
    const float* W_att = (const float*)d_in[6];
    const float* b_att = (const float*)d_in[7];
    float* out = (float*)d_out;

    prep_kernel<<<512, 256>>>(W_ih, W_hh, b_ih, b_hh);
    cudaFuncSetAttribute(lstm_mma_kernel,
                         cudaFuncAttributeMaxDynamicSharedMemorySize, S_TOT);
    lstm_mma_kernel<<<NGR / MM, NTH, S_TOT>>>(x);
    const int att_smem = (32768 + 256 + 1024) * 4;
    cudaFuncSetAttribute(att_kernel,
                         cudaFuncAttributeMaxDynamicSharedMemorySize, att_smem);
    att_kernel<<<NGR / AG, 256, att_smem>>>(W_att, b_att, out);
}